// round 16
// baseline (speedup 1.0000x reference)
#include <cuda_runtime.h>

#define BB 1024
#define DD 256
#define HH 32

#define ONE2 0x3F8000003F800000ULL

// packed f32x2 ops (Blackwell): 2 lanes per instruction
#define FMA2(d, a, b, c) asm("fma.rn.f32x2 %0, %1, %2, %3;" : "=l"(d) : "l"(a), "l"(b), "l"(c))
#define MUL2(d, a, b)    asm("mul.rn.f32x2 %0, %1, %2;"     : "=l"(d) : "l"(a), "l"(b))

__device__ __forceinline__ ulonglong2 ldg4(const float4* p) {
    return __ldg((const ulonglong2*)p);
}
__device__ __forceinline__ float2 unpack2(unsigned long long v) {
    float2 r;
    asm("mov.b64 {%0, %1}, %2;" : "=f"(r.x), "=f"(r.y) : "l"(v));
    return r;
}

// Column tables: exp(+W)/exp(-W) packed by j-quad: float4 element [jq*DD + k]
// holds (e_{4jq}, e_{4jq+1}, e_{4jq+2}, e_{4jq+3}) -> one LDG.128 per 4 factors.
// Row tables: [DD][HH] — coalesced across j for the rank-1 gather.
__device__ float4 g_ewp4[8 * DD];
__device__ float4 g_ewm4[8 * DD];
__device__ float  g_ewpR[DD * HH];
__device__ float  g_ewmR[DD * HH];
__device__ float2 g_eb[DD];          // (exp(+b/2), exp(-b/2))
__device__ float  g_E[BB * HH];      // E_j(row) = exp((x@W)_j + c_j)

// Prep: blocks 0..7 build tables; blocks 8..8+BB/8-1 compute E, 8 rows per block.
__global__ __launch_bounds__(256) void prep_kernel(
    const float* __restrict__ x,
    const float* __restrict__ W,
    const float* __restrict__ b,
    const float* __restrict__ c)
{
    const int bid = blockIdx.x;
    const int tid = threadIdx.x;
    if (bid < 8) {
        for (int t = bid * 256 + tid; t < DD * HH; t += 8 * 256) {
            int d = t >> 5;
            int j = t & 31;
            float w  = W[t];
            float ep = expf(w);
            float em = expf(-w);
            int idx = ((j >> 2) * DD + d) * 4 + (j & 3);
            ((float*)g_ewp4)[idx] = ep;
            ((float*)g_ewm4)[idx] = em;
            g_ewpR[t] = ep;
            g_ewmR[t] = em;
        }
        int t = bid * 256 + tid;
        if (t < DD) {
            float bv = b[t];
            g_eb[t] = make_float2(expf(0.5f * bv), expf(-0.5f * bv));
        }
        cudaTriggerProgrammaticLaunchCompletion();
        return;
    }

    __shared__ float ap[8][8][32];           // [warp][row][j]
    const int row0 = (bid - 8) * 8;
    const int w    = tid >> 5;
    const int lane = tid & 31;

    unsigned m[8];
    #pragma unroll
    for (int r = 0; r < 8; ++r)
        m[r] = __ballot_sync(0xffffffffu, x[(row0 + r) * DD + w * 32 + lane] != 0.0f);

    const float* Wb = W + (w * 32) * HH + lane;
    float acc[8] = {0.f, 0.f, 0.f, 0.f, 0.f, 0.f, 0.f, 0.f};
    #pragma unroll
    for (int i = 0; i < 32; ++i) {
        float wv = Wb[i * HH];
        #pragma unroll
        for (int r = 0; r < 8; ++r)
            if (m[r] & (1u << i)) acc[r] += wv;
    }
    #pragma unroll
    for (int r = 0; r < 8; ++r) ap[w][r][lane] = acc[r];
    __syncthreads();

    float a = c[lane];
    #pragma unroll
    for (int ww = 0; ww < 8; ++ww) a += ap[ww][w][lane];
    g_E[(row0 + w) * HH + lane] = expf(a);
    cudaTriggerProgrammaticLaunchCompletion();
}

__device__ __forceinline__ unsigned fmono(float f) {
    unsigned u = __float_as_uint(f);
    return (u & 0x80000000u) ? ~u : (u | 0x80000000u);
}

// R10 structure: 128 threads, 2 dims/thread, grid 1024, PDL; f32x2 math +
// LDG.128 table loads.
__global__ __launch_bounds__(128, 8) void gwg_kernel(
    const float* __restrict__ x,
    const float* __restrict__ gum,
    const float* __restrict__ acc,
    float* __restrict__ out)
{
    __shared__ float xs[DD];
    __shared__ __align__(16) float sEf[4][HH];   // per-warp copy of E_j
    __shared__ __align__(16) float sE2[4][HH];   // per-warp copy of E'_j
    __shared__ float sredf[4];
    __shared__ uint2 sredk[4];                   // (fmono(key), idx) per warp

    const int row  = blockIdx.x;
    const int tid  = threadIdx.x;
    const int w    = tid >> 5;
    const int lane = tid & 31;
    const int k0   = tid;          // dims tid and tid+128
    const int k1   = tid + 128;

    // prep-independent front work (overlaps prep via PDL)
    float xk0 = x[row * DD + k0];
    float xk1 = x[row * DD + k1];
    float u0  = gum[row * DD + k0];
    float u1  = gum[row * DD + k1];
    float au  = acc[row];
    xs[k0] = xk0;
    xs[k1] = xk1;
    float z0 = -logf(u0 + 1e-9f) + 1e-9f;
    float z1 = -logf(u1 + 1e-9f) + 1e-9f;

    cudaGridDependencySynchronize();

    float2 eb0 = g_eb[k0];
    float2 eb1 = g_eb[k1];

    // each warp keeps its own E copy -> no cross-warp wait
    float E = g_E[row * HH + lane];
    sEf[w][lane] = E;
    __syncwarp();

    // ---- forward: packed products of (1 + E_j e^{delta w}) over j ----
    const float4* t0 = (xk0 == 0.0f) ? g_ewp4 : g_ewm4;
    const float4* t1 = (xk1 == 0.0f) ? g_ewp4 : g_ewm4;
    const float ebf0 = (xk0 == 0.0f) ? eb0.x : eb0.y;
    const float ebf1 = (xk1 == 0.0f) ? eb1.x : eb1.y;
    const ulonglong2* E16 = (const ulonglong2*)sEf[w];

    unsigned long long pA0 = ONE2, pA1 = ONE2;   // dim k0, two j-pair lanes
    unsigned long long pB0 = ONE2, pB1 = ONE2;   // dim k1
    #pragma unroll
    for (int jq = 0; jq < 8; ++jq) {
        ulonglong2 Ev = E16[jq];                 // E for j = 4jq .. 4jq+3
        ulonglong2 eA = ldg4(&t0[jq * DD + k0]); // 4 factors, dim k0
        ulonglong2 eB = ldg4(&t1[jq * DD + k1]); // 4 factors, dim k1
        unsigned long long f;
        FMA2(f, Ev.x, eA.x, ONE2);  MUL2(pA0, pA0, f);
        FMA2(f, Ev.y, eA.y, ONE2);  MUL2(pA1, pA1, f);
        FMA2(f, Ev.x, eB.x, ONE2);  MUL2(pB0, pB0, f);
        FMA2(f, Ev.y, eB.y, ONE2);  MUL2(pB1, pB1, f);
    }
    float2 a0 = unpack2(pA0), a1 = unpack2(pA1);
    float2 b0 = unpack2(pB0), b1 = unpack2(pB1);
    float ek0 = ebf0 * sqrtf((a0.x * a0.y) * (a1.x * a1.y));
    float ek1 = ebf1 * sqrtf((b0.x * b0.y) * (b1.x * b1.y));

    // gumbel-max in exp domain: argmax(l+g) == argmax(ek / z); keys > 0
    float key0 = ek0 / z0;
    float key1 = ek1 / z1;

    float key; int ki;
    if (key0 >= key1) { key = key0; ki = k0; } else { key = key1; ki = k1; }

    // warp sum (5 shfl) + warp argmax (redux + ballot + 1 shfl)
    float s = ek0 + ek1;
    #pragma unroll
    for (int off = 16; off; off >>= 1) s += __shfl_xor_sync(0xffffffffu, s, off);
    unsigned km   = fmono(key);
    unsigned wmax = __reduce_max_sync(0xffffffffu, km);
    unsigned ball = __ballot_sync(0xffffffffu, km == wmax);
    int      wki  = __shfl_sync(0xffffffffu, ki, __ffs(ball) - 1);
    if (lane == 0) { sredf[w] = s; sredk[w] = make_uint2(wmax, (unsigned)wki); }
    __syncthreads();                           // B2 (genuine combine)

    // ---- every thread combines 4 warp partials via broadcast LDS ----
    float Sf;
    int   kstar;
    {
        Sf = (sredf[0] + sredf[1]) + (sredf[2] + sredf[3]);
        uint2 c0 = sredk[0], c1 = sredk[1], c2 = sredk[2], c3 = sredk[3];
        uint2 mA = (c1.x > c0.x || (c1.x == c0.x && c1.y < c0.y)) ? c1 : c0;
        uint2 mB = (c3.x > c2.x || (c3.x == c2.x && c3.y < c2.y)) ? c3 : c2;
        uint2 mm = (mB.x > mA.x || (mB.x == mA.x && mB.y < mA.y)) ? mB : mA;
        kstar = (int)mm.y;
    }

    // ---- rank-1 update, per-warp redundant: coalesced row read; R in register ----
    float Rt;
    {
        float xks = xs[kstar];                 // visible: written pre-B2
        const float* rowt = (xks == 0.0f) ? g_ewpR : g_ewmR;
        float mj  = __ldg(&rowt[kstar * HH + lane]);
        float E2  = E * mj;
        sE2[w][lane] = E2;
        float rr = (1.f + E2) / (1.f + E);
        #pragma unroll
        for (int off = 16; off; off >>= 1) rr *= __shfl_xor_sync(0xffffffffu, rr, off);
        Rt = rr;
        __syncwarp();
    }

    // ---- reverse pass at x_delta: tables flip only for the kstar dim ----
    const float4* t0r = (k0 == kstar) ? ((xk0 == 0.0f) ? g_ewm4 : g_ewp4) : t0;
    const float4* t1r = (k1 == kstar) ? ((xk1 == 0.0f) ? g_ewm4 : g_ewp4) : t1;
    const float ebr0 = (k0 == kstar) ? ((xk0 == 0.0f) ? eb0.y : eb0.x) : ebf0;
    const float ebr1 = (k1 == kstar) ? ((xk1 == 0.0f) ? eb1.y : eb1.x) : ebf1;
    const ulonglong2* F16 = (const ulonglong2*)sE2[w];

    unsigned long long qA0 = ONE2, qA1 = ONE2;
    unsigned long long qB0 = ONE2, qB1 = ONE2;
    #pragma unroll
    for (int jq = 0; jq < 8; ++jq) {
        ulonglong2 Ev = F16[jq];
        ulonglong2 eA = ldg4(&t0r[jq * DD + k0]);
        ulonglong2 eB = ldg4(&t1r[jq * DD + k1]);
        unsigned long long f;
        FMA2(f, Ev.x, eA.x, ONE2);  MUL2(qA0, qA0, f);
        FMA2(f, Ev.y, eA.y, ONE2);  MUL2(qA1, qA1, f);
        FMA2(f, Ev.x, eB.x, ONE2);  MUL2(qB0, qB0, f);
        FMA2(f, Ev.y, eB.y, ONE2);  MUL2(qB1, qB1, f);
    }
    float2 c0v = unpack2(qA0), c1v = unpack2(qA1);
    float2 d0v = unpack2(qB0), d1v = unpack2(qB1);
    float er0 = ebr0 * sqrtf((c0v.x * c0v.y) * (c1v.x * c1v.y));
    float er1 = ebr1 * sqrtf((d0v.x * d0v.y) * (d1v.x * d1v.y));

    float s2 = er0 + er1;
    #pragma unroll
    for (int off = 16; off; off >>= 1) s2 += __shfl_xor_sync(0xffffffffu, s2, off);
    if (lane == 0) sredf[w] = s2;
    __syncthreads();                           // B4 (genuine combine)

    float Sr = (sredf[0] + sredf[1]) + (sredf[2] + sredf[3]);

    // ---- accept: Zf/Zr = sqrt(R) * Sf / Sr > u ----
    bool accv = sqrtf(Rt) * Sf > au * Sr;
    out[row * DD + k0] = (k0 == kstar && accv) ? (1.f - xk0) : xk0;
    out[row * DD + k1] = (k1 == kstar && accv) ? (1.f - xk1) : xk1;
}

extern "C" void kernel_launch(void* const* d_in, const int* in_sizes, int n_in,
                              void* d_out, int out_size) {
    const float* x   = (const float*)d_in[0];
    const float* W   = (const float*)d_in[1];
    const float* b   = (const float*)d_in[2];
    const float* c   = (const float*)d_in[3];
    const float* gum = (const float*)d_in[4];
    const float* acc = (const float*)d_in[5];
    float* out = (float*)d_out;

    prep_kernel<<<8 + BB / 8, 256>>>(x, W, b, c);

    cudaLaunchConfig_t cfg = {};
    cfg.gridDim  = dim3(BB, 1, 1);
    cfg.blockDim = dim3(128, 1, 1);
    cfg.dynamicSmemBytes = 0;
    cfg.stream = 0;
    cudaLaunchAttribute attrs[1];
    attrs[0].id = cudaLaunchAttributeProgrammaticStreamSerialization;
    attrs[0].val.programmaticStreamSerializationAllowed = 1;
    cfg.attrs = attrs;
    cfg.numAttrs = 1;
    cudaLaunchKernelEx(&cfg, gwg_kernel, x, gum, acc, out);
}